// round 1
// baseline (speedup 1.0000x reference)
#include <cuda_runtime.h>
#include <cstdint>

// Problem constants
#define Bn 4
#define Ln 896
#define Dn 2048
#define HQn 32
#define HKVn 8
#define HDn 64
#define GROUPn 4
#define TPF 7
#define MROWS (Bn * Ln)      // 3584
#define NKV (HKVn * HDn)     // 512

// Scratch (no allocation allowed -> device globals)
__device__ float g_q[MROWS * Dn];
__device__ float g_k[MROWS * NKV];
__device__ float g_v[MROWS * NKV];
__device__ float g_attn[MROWS * Dn];

// ---------------------------------------------------------------------------
// SGEMM: C[M,N] = A[M,K] @ B[K,N], all row-major fp32.
// 128x128 block tile, K-tile 8, 256 threads, 8x8 per-thread microtile.
// Requires M%128==0, N%128==0, K%8==0 (true for all 4 calls here).
// ---------------------------------------------------------------------------
__global__ __launch_bounds__(256) void sgemm_kernel(
    const float* __restrict__ A, const float* __restrict__ Bm,
    float* __restrict__ C, int Mdim, int Ndim, int Kdim)
{
    __shared__ float As[8][128];   // k-major
    __shared__ float Bs[8][128];

    const int tid = threadIdx.x;
    const int bm = blockIdx.y * 128;
    const int bn = blockIdx.x * 128;
    const int tx = tid & 15;
    const int ty = tid >> 4;

    const int arow = tid >> 1;       // 0..127
    const int aseg = tid & 1;        // 0..1 (two float4 per 8-wide row)
    const int brow = tid >> 5;       // 0..7
    const int bc4  = tid & 31;       // 0..31

    const float* Aptr = A + (size_t)(bm + arow) * Kdim + aseg * 4;
    const float* Bptr = Bm + (size_t)brow * Ndim + bn + bc4 * 4;

    float acc[8][8];
#pragma unroll
    for (int i = 0; i < 8; i++)
#pragma unroll
        for (int j = 0; j < 8; j++) acc[i][j] = 0.0f;

    for (int k0 = 0; k0 < Kdim; k0 += 8) {
        float4 av = *(const float4*)(Aptr + k0);
        float4 bv = *(const float4*)(Bptr + (size_t)k0 * Ndim);
        As[aseg * 4 + 0][arow] = av.x;
        As[aseg * 4 + 1][arow] = av.y;
        As[aseg * 4 + 2][arow] = av.z;
        As[aseg * 4 + 3][arow] = av.w;
        *(float4*)(&Bs[brow][bc4 * 4]) = bv;
        __syncthreads();

#pragma unroll
        for (int kk = 0; kk < 8; kk++) {
            float4 a0 = *(const float4*)&As[kk][ty * 8];
            float4 a1 = *(const float4*)&As[kk][ty * 8 + 4];
            float4 b0 = *(const float4*)&Bs[kk][tx * 8];
            float4 b1 = *(const float4*)&Bs[kk][tx * 8 + 4];
            float a[8] = {a0.x, a0.y, a0.z, a0.w, a1.x, a1.y, a1.z, a1.w};
            float b[8] = {b0.x, b0.y, b0.z, b0.w, b1.x, b1.y, b1.z, b1.w};
#pragma unroll
            for (int i = 0; i < 8; i++)
#pragma unroll
                for (int j = 0; j < 8; j++)
                    acc[i][j] = fmaf(a[i], b[j], acc[i][j]);
        }
        __syncthreads();
    }

#pragma unroll
    for (int i = 0; i < 8; i++) {
        float* cp = C + (size_t)(bm + ty * 8 + i) * Ndim + bn + tx * 8;
        float4 v0 = make_float4(acc[i][0], acc[i][1], acc[i][2], acc[i][3]);
        float4 v1 = make_float4(acc[i][4], acc[i][5], acc[i][6], acc[i][7]);
        *(float4*)cp = v0;
        *(float4*)(cp + 4) = v1;
    }
}

// ---------------------------------------------------------------------------
// RoPE over q (32 heads) and k (8 heads), interleaved-pair convention.
// One thread per (row, head, pair).
// ---------------------------------------------------------------------------
__global__ void rope_kernel(const int* __restrict__ pos_ids)
{
    const int half = HDn / 2;
    int idx = blockIdx.x * blockDim.x + threadIdx.x;
    const int total = MROWS * (HQn + HKVn) * half;
    if (idx >= total) return;

    int j = idx % half;
    int rest = idx / half;
    int h = rest % (HQn + HKVn);
    int row = rest / (HQn + HKVn);   // b*L + l
    int l = row % Ln;

    float pos = (float)pos_ids[l];
    float inv = expf(-logf(10000.0f) * ((float)j / (float)half));
    float ang = pos * inv;
    float c = cosf(ang);
    float s = sinf(ang);

    float* base;
    if (h < HQn) base = &g_q[(size_t)row * Dn + h * HDn];
    else         base = &g_k[(size_t)row * NKV + (h - HQn) * HDn];

    float x1 = base[2 * j];
    float x2 = base[2 * j + 1];
    base[2 * j]     = x1 * c - x2 * s;
    base[2 * j + 1] = x1 * s + x2 * c;
}

// ---------------------------------------------------------------------------
// Flash-style attention. Block = (q-tile of 64, head, batch). 256 threads.
// S = Q K^T (4x4 microtiles, d-major smem with stride-65 padding),
// online softmax with register row-stats + 16-lane shuffle reductions,
// P reuses the K smem buffer, O accumulated in registers.
// Frame-causal mask: key m allowed iff m/7 <= l/7.
// ---------------------------------------------------------------------------
#define QS_STRIDE 65
#define VS_STRIDE 68
#define ATTN_SMEM_FLOATS (64 * QS_STRIDE * 2 + 64 * VS_STRIDE)
#define ATTN_SMEM_BYTES (ATTN_SMEM_FLOATS * 4)

__global__ __launch_bounds__(256) void attn_kernel(float* __restrict__ o)
{
    extern __shared__ float sm[];
    float* qs = sm;                        // qs[d*65 + r]   (d-major)
    float* ks = sm + 64 * QS_STRIDE;       // ks[d*65 + c], reused as P[r*65 + m]
    float* vs = sm + 2 * 64 * QS_STRIDE;   // vs[m*68 + d]

    const int qt = blockIdx.x;
    const int h  = blockIdx.y;
    const int b  = blockIdx.z;
    const int l0 = qt * 64;
    const int kh = h >> 2;   // GQA: 4 q-heads per kv-head

    const int tid = threadIdx.x;
    const int tx = tid & 15;
    const int ty = tid >> 4;

    // Load Q tile transposed into qs[d][r]
#pragma unroll
    for (int it = 0; it < 4; it++) {
        int idx = tid + it * 256;
        int r = idx >> 4, c4 = idx & 15;
        float4 qv = *(const float4*)&g_q[(size_t)(b * Ln + l0 + r) * Dn + h * HDn + c4 * 4];
        qs[(c4 * 4 + 0) * QS_STRIDE + r] = qv.x;
        qs[(c4 * 4 + 1) * QS_STRIDE + r] = qv.y;
        qs[(c4 * 4 + 2) * QS_STRIDE + r] = qv.z;
        qs[(c4 * 4 + 3) * QS_STRIDE + r] = qv.w;
    }

    float acc[4][4];
    float rm[4], rs[4];
#pragma unroll
    for (int i = 0; i < 4; i++) {
        rm[i] = -1e30f;
        rs[i] = 0.0f;
#pragma unroll
        for (int j = 0; j < 4; j++) acc[i][j] = 0.0f;
    }

    int row_maxm[4];
#pragma unroll
    for (int i = 0; i < 4; i++) {
        int l = l0 + 4 * ty + i;
        row_maxm[i] = (l / TPF) * TPF + TPF - 1;
    }
    int maxm = ((l0 + 63) / TPF) * TPF + TPF - 1;
    if (maxm > Ln - 1) maxm = Ln - 1;
    const int nkt = maxm / 64 + 1;
    const int q0fid = l0 / TPF;

    for (int kt = 0; kt < nkt; kt++) {
        const int m0 = kt * 64;
        __syncthreads();   // protect ks/vs from previous iteration
        // Load K tile transposed, V tile direct
#pragma unroll
        for (int it = 0; it < 4; it++) {
            int idx = tid + it * 256;
            int r = idx >> 4, c4 = idx & 15;
            size_t grow = (size_t)(b * Ln + m0 + r) * NKV + kh * HDn + c4 * 4;
            float4 kv = *(const float4*)&g_k[grow];
            ks[(c4 * 4 + 0) * QS_STRIDE + r] = kv.x;
            ks[(c4 * 4 + 1) * QS_STRIDE + r] = kv.y;
            ks[(c4 * 4 + 2) * QS_STRIDE + r] = kv.z;
            ks[(c4 * 4 + 3) * QS_STRIDE + r] = kv.w;
            float4 vv = *(const float4*)&g_v[grow];
            *(float4*)&vs[r * VS_STRIDE + c4 * 4] = vv;
        }
        __syncthreads();

        // S = Q K^T
        float s[4][4];
#pragma unroll
        for (int i = 0; i < 4; i++)
#pragma unroll
            for (int j = 0; j < 4; j++) s[i][j] = 0.0f;
#pragma unroll 8
        for (int d = 0; d < 64; d++) {
            float qv[4], kv[4];
#pragma unroll
            for (int i = 0; i < 4; i++) qv[i] = qs[d * QS_STRIDE + 4 * ty + i];
#pragma unroll
            for (int j = 0; j < 4; j++) kv[j] = ks[d * QS_STRIDE + 4 * tx + j];
#pragma unroll
            for (int i = 0; i < 4; i++)
#pragma unroll
                for (int j = 0; j < 4; j++)
                    s[i][j] = fmaf(qv[i], kv[j], s[i][j]);
        }

        const bool full = ((m0 + 63) / TPF) <= q0fid;
        const float scale = 0.125f;   // 1/sqrt(64)
#pragma unroll
        for (int i = 0; i < 4; i++)
#pragma unroll
            for (int j = 0; j < 4; j++) {
                s[i][j] *= scale;
                if (!full) {
                    int m = m0 + 4 * tx + j;
                    if (m > row_maxm[i]) s[i][j] = -1e30f;
                }
            }

        // Online softmax (row stats replicated across 16 tx lanes)
        float p[4][4];
#pragma unroll
        for (int i = 0; i < 4; i++) {
            float tm = s[i][0];
#pragma unroll
            for (int j = 1; j < 4; j++) tm = fmaxf(tm, s[i][j]);
#pragma unroll
            for (int off = 8; off >= 1; off >>= 1)
                tm = fmaxf(tm, __shfl_xor_sync(0xffffffffu, tm, off));
            float nm = fmaxf(rm[i], tm);
            float fac = expf(rm[i] - nm);
            float ls = 0.0f;
#pragma unroll
            for (int j = 0; j < 4; j++) {
                p[i][j] = expf(s[i][j] - nm);
                ls += p[i][j];
            }
#pragma unroll
            for (int off = 8; off >= 1; off >>= 1)
                ls += __shfl_xor_sync(0xffffffffu, ls, off);
            rs[i] = rs[i] * fac + ls;
            rm[i] = nm;
#pragma unroll
            for (int j = 0; j < 4; j++) acc[i][j] *= fac;
        }

        __syncthreads();   // done reading ks as K -> reuse as P
#pragma unroll
        for (int i = 0; i < 4; i++)
#pragma unroll
            for (int j = 0; j < 4; j++)
                ks[(4 * ty + i) * QS_STRIDE + 4 * tx + j] = p[i][j];
        __syncthreads();

        // O += P V
#pragma unroll 8
        for (int m = 0; m < 64; m++) {
            float pv[4], vv[4];
#pragma unroll
            for (int i = 0; i < 4; i++) pv[i] = ks[(4 * ty + i) * QS_STRIDE + m];
#pragma unroll
            for (int j = 0; j < 4; j++) vv[j] = vs[m * VS_STRIDE + 4 * tx + j];
#pragma unroll
            for (int i = 0; i < 4; i++)
#pragma unroll
                for (int j = 0; j < 4; j++)
                    acc[i][j] = fmaf(pv[i], vv[j], acc[i][j]);
        }
    }

    // Normalize and write out: o[b, l, h, d]
#pragma unroll
    for (int i = 0; i < 4; i++) {
        float inv = 1.0f / rs[i];
        float4 o4 = make_float4(acc[i][0] * inv, acc[i][1] * inv,
                                acc[i][2] * inv, acc[i][3] * inv);
        *(float4*)&o[(size_t)(b * Ln + l0 + 4 * ty + i) * Dn + h * HDn + 4 * tx] = o4;
    }
}

// ---------------------------------------------------------------------------
// Launch
// ---------------------------------------------------------------------------
extern "C" void kernel_launch(void* const* d_in, const int* in_sizes, int n_in,
                              void* d_out, int out_size)
{
    const float* x   = (const float*)d_in[0];
    const float* wq  = (const float*)d_in[1];
    const float* wk  = (const float*)d_in[2];
    const float* wv  = (const float*)d_in[3];
    const float* wo  = (const float*)d_in[4];
    const int*   pos = (const int*)d_in[5];
    float* out = (float*)d_out;

    float *q, *k, *v, *attn;
    cudaGetSymbolAddress((void**)&q,    g_q);
    cudaGetSymbolAddress((void**)&k,    g_k);
    cudaGetSymbolAddress((void**)&v,    g_v);
    cudaGetSymbolAddress((void**)&attn, g_attn);

    cudaFuncSetAttribute((const void*)attn_kernel,
                         cudaFuncAttributeMaxDynamicSharedMemorySize,
                         ATTN_SMEM_BYTES);

    dim3 gq(Dn / 128, MROWS / 128);     // 16 x 28
    dim3 gkv(NKV / 128, MROWS / 128);   // 4 x 28

    sgemm_kernel<<<gq, 256>>>(x, wq, q, MROWS, Dn, Dn);
    sgemm_kernel<<<gkv, 256>>>(x, wk, k, MROWS, NKV, Dn);
    sgemm_kernel<<<gkv, 256>>>(x, wv, v, MROWS, NKV, Dn);

    int total = MROWS * (HQn + HKVn) * (HDn / 2);
    rope_kernel<<<(total + 255) / 256, 256>>>(pos);

    dim3 ga(Ln / 64, HQn, Bn);
    attn_kernel<<<ga, 256, ATTN_SMEM_BYTES>>>(attn);

    sgemm_kernel<<<gq, 256>>>(attn, wo, out, MROWS, Dn, Dn);
}

// round 4
// speedup vs baseline: 2.6779x; 2.6779x over previous
#include <cuda_runtime.h>
#include <cuda_bf16.h>
#include <cstdint>

// Problem constants
#define Bn 4
#define Ln 896
#define Dn 2048
#define HQn 32
#define HKVn 8
#define HDn 64
#define TPF 7
#define MROWS (Bn * Ln)      // 3584
#define NKV (HKVn * HDn)     // 512

// Scratch (no allocation allowed -> device globals)
__device__ float g_q[MROWS * Dn];
__device__ float g_k[MROWS * NKV];
__device__ float g_v[MROWS * NKV];
__device__ float g_attn[MROWS * Dn];

// Split bf16 operand buffers
__device__ __nv_bfloat16 g_xh[MROWS * Dn],  g_xl[MROWS * Dn];
__device__ __nv_bfloat16 g_wqh[Dn * Dn],    g_wql[Dn * Dn];
__device__ __nv_bfloat16 g_wkh[Dn * NKV],   g_wkl[Dn * NKV];
__device__ __nv_bfloat16 g_wvh[Dn * NKV],   g_wvl[Dn * NKV];
__device__ __nv_bfloat16 g_woh[Dn * Dn],    g_wol[Dn * Dn];
__device__ __nv_bfloat16 g_ah[MROWS * Dn],  g_al[MROWS * Dn];

__device__ __forceinline__ uint32_t smem_u32(const void* p) {
    uint32_t a;
    asm("{ .reg .u64 t; cvta.to.shared.u64 t, %1; cvt.u32.u64 %0, t; }"
        : "=r"(a) : "l"(p));
    return a;
}

#define CP_ASYNC16(dst, src) \
    asm volatile("cp.async.cg.shared.global [%0], [%1], 16;" :: "r"(dst), "l"(src))
#define CP_COMMIT() asm volatile("cp.async.commit_group;" ::: "memory")
#define CP_WAIT1()  asm volatile("cp.async.wait_group 1;" ::: "memory")

#define MMA_BF16(cc, a, b) \
    asm volatile( \
        "mma.sync.aligned.m16n8k16.row.col.f32.bf16.bf16.f32 " \
        "{%0,%1,%2,%3}, {%4,%5,%6,%7}, {%8,%9}, {%0,%1,%2,%3};" \
        : "+f"((cc)[0]), "+f"((cc)[1]), "+f"((cc)[2]), "+f"((cc)[3]) \
        : "r"((a)[0]), "r"((a)[1]), "r"((a)[2]), "r"((a)[3]), \
          "r"((b)[0]), "r"((b)[1]))

// ---------------------------------------------------------------------------
// Split fp32 -> (bf16 hi, bf16 lo). n must be divisible by 4.
// ---------------------------------------------------------------------------
__global__ void split_kernel(const float* __restrict__ src,
                             __nv_bfloat16* __restrict__ hi,
                             __nv_bfloat16* __restrict__ lo, int n4)
{
    int i = blockIdx.x * blockDim.x + threadIdx.x;
    if (i >= n4) return;
    float4 v = ((const float4*)src)[i];
    __nv_bfloat16 h0 = __float2bfloat16_rn(v.x);
    __nv_bfloat16 h1 = __float2bfloat16_rn(v.y);
    __nv_bfloat16 h2 = __float2bfloat16_rn(v.z);
    __nv_bfloat16 h3 = __float2bfloat16_rn(v.w);
    __nv_bfloat16 l0 = __float2bfloat16_rn(v.x - __bfloat162float(h0));
    __nv_bfloat16 l1 = __float2bfloat16_rn(v.y - __bfloat162float(h1));
    __nv_bfloat16 l2 = __float2bfloat16_rn(v.z - __bfloat162float(h2));
    __nv_bfloat16 l3 = __float2bfloat16_rn(v.w - __bfloat162float(h3));
    ((__nv_bfloat162*)hi)[2 * i]     = __nv_bfloat162(h0, h1);
    ((__nv_bfloat162*)hi)[2 * i + 1] = __nv_bfloat162(h2, h3);
    ((__nv_bfloat162*)lo)[2 * i]     = __nv_bfloat162(l0, l1);
    ((__nv_bfloat162*)lo)[2 * i + 1] = __nv_bfloat162(l2, l3);
}

// ---------------------------------------------------------------------------
// Split-bf16 GEMM: C[M,N] = (Ah+Al)[M,K] @ (Bh+Bl)[K,N] (3-term, fp32 accum).
// CTA 128x128, K-tile 32, 8 warps (2M x 4N), warp tile 64x32.
// 3-stage cp.async pipeline. Requires M%128==0, N%128==0, K%32==0.
// SMEM per stage: A (hi|lo packed per 128B row) 16KB, Bh 8KB, Bl 8KB.
// ---------------------------------------------------------------------------
#define STAGE_BYTES (16384 + 8192 + 8192)
#define GEMM_STAGES 3
#define GEMM_SMEM_BYTES (GEMM_STAGES * STAGE_BYTES)

__global__ __launch_bounds__(256) void gemm_bf16x3_kernel(
    const __nv_bfloat16* __restrict__ Ah, const __nv_bfloat16* __restrict__ Al,
    const __nv_bfloat16* __restrict__ Bh, const __nv_bfloat16* __restrict__ Bl,
    float* __restrict__ C, int Ndim, int Kdim)
{
    extern __shared__ char smraw[];
    const uint32_t smb = smem_u32(smraw);
    const int tid = threadIdx.x;
    const int wid = tid >> 5;
    const int lane = tid & 31;
    const int bm = blockIdx.y * 128;
    const int bn = blockIdx.x * 128;
    const int wm = wid >> 2;      // 0..1
    const int wn = wid & 3;       // 0..3

    float c[4][4][4];
#pragma unroll
    for (int mt = 0; mt < 4; mt++)
#pragma unroll
        for (int nt = 0; nt < 4; nt++)
#pragma unroll
            for (int r = 0; r < 4; r++) c[mt][nt][r] = 0.0f;

    const int nk = Kdim / 32;

    // A tile: 128 rows x 128B. Row m: chunks 0-3 = hi k0..31, chunks 4-7 = lo.
    // Physical chunk = logical chunk ^ (row & 7)  (SW128).
    // B tiles (hi, lo): 32 k-rows x 256B; phys chunk = (n/8) ^ (k & 7).
#define LOAD_TILE(s, k0) do { \
        uint32_t baseA = smb + (s) * STAGE_BYTES; \
        uint32_t baseBh = baseA + 16384; \
        uint32_t baseBl = baseBh + 8192; \
        const int ca = tid & 7; \
        _Pragma("unroll") \
        for (int it = 0; it < 4; it++) { \
            int row = (tid >> 3) + it * 32; \
            const __nv_bfloat16* src = (ca < 4) \
                ? Ah + (size_t)(bm + row) * Kdim + (k0) + ca * 8 \
                : Al + (size_t)(bm + row) * Kdim + (k0) + (ca - 4) * 8; \
            CP_ASYNC16(baseA + row * 128 + ((ca ^ (row & 7)) << 4), src); \
        } \
        const int cb = tid & 15; \
        _Pragma("unroll") \
        for (int it = 0; it < 2; it++) { \
            int kr = (tid >> 4) + it * 16; \
            uint32_t off = kr * 256 + ((cb ^ (kr & 7)) << 4); \
            CP_ASYNC16(baseBh + off, Bh + (size_t)((k0) + kr) * Ndim + bn + cb * 8); \
            CP_ASYNC16(baseBl + off, Bl + (size_t)((k0) + kr) * Ndim + bn + cb * 8); \
        } \
    } while (0)

    LOAD_TILE(0, 0);
    CP_COMMIT();
    LOAD_TILE(1, 32);
    CP_COMMIT();

    // Fragment addressing (constant per lane)
    const int a_row_l = (lane & 15);           // row within 16-row block
    const int a_inner = (lane >> 4) & 1;       // k8 chunk within k16
    const int b_krow_l = ((lane >> 3) & 1) * 8 + (lane & 7);
    const int b_nch = (lane >> 4) & 1;

    for (int i = 0; i < nk; i++) {
        CP_WAIT1();
        __syncthreads();

        if (i + 2 < nk) {
            int s = (i + 2) % GEMM_STAGES;
            LOAD_TILE(s, (i + 2) * 32);
        }
        CP_COMMIT();

        const int buf = i % GEMM_STAGES;
        const uint32_t smA  = smb + buf * STAGE_BYTES;
        const uint32_t smBh = smA + 16384;
        const uint32_t smBl = smBh + 8192;

#pragma unroll
        for (int kk = 0; kk < 2; kk++) {
            uint32_t ah[4][4], al[4][4];
#pragma unroll
            for (int mt = 0; mt < 4; mt++) {
                int row = wm * 64 + mt * 16 + a_row_l;
                int lch = kk * 2 + a_inner;          // hi: 0..3
                uint32_t offh = smA + row * 128 + (((lch) ^ (row & 7)) << 4);
                uint32_t offl = smA + row * 128 + (((lch + 4) ^ (row & 7)) << 4);
                asm volatile(
                    "ldmatrix.sync.aligned.m8n8.x4.shared.b16 {%0,%1,%2,%3}, [%4];"
                    : "=r"(ah[mt][0]), "=r"(ah[mt][1]), "=r"(ah[mt][2]), "=r"(ah[mt][3])
                    : "r"(offh));
                asm volatile(
                    "ldmatrix.sync.aligned.m8n8.x4.shared.b16 {%0,%1,%2,%3}, [%4];"
                    : "=r"(al[mt][0]), "=r"(al[mt][1]), "=r"(al[mt][2]), "=r"(al[mt][3])
                    : "r"(offl));
            }
            uint32_t bh[4][2], bl[4][2];
#pragma unroll
            for (int p = 0; p < 2; p++) {
                int kr = kk * 16 + b_krow_l;
                int nchunk = wn * 4 + p * 2 + b_nch;
                uint32_t off = kr * 256 + ((nchunk ^ (kr & 7)) << 4);
                uint32_t r0, r1, r2, r3;
                asm volatile(
                    "ldmatrix.sync.aligned.m8n8.x4.trans.shared.b16 {%0,%1,%2,%3}, [%4];"
                    : "=r"(r0), "=r"(r1), "=r"(r2), "=r"(r3)
                    : "r"(smBh + off));
                bh[2 * p][0] = r0; bh[2 * p][1] = r1;
                bh[2 * p + 1][0] = r2; bh[2 * p + 1][1] = r3;
                asm volatile(
                    "ldmatrix.sync.aligned.m8n8.x4.trans.shared.b16 {%0,%1,%2,%3}, [%4];"
                    : "=r"(r0), "=r"(r1), "=r"(r2), "=r"(r3)
                    : "r"(smBl + off));
                bl[2 * p][0] = r0; bl[2 * p][1] = r1;
                bl[2 * p + 1][0] = r2; bl[2 * p + 1][1] = r3;
            }
#pragma unroll
            for (int mt = 0; mt < 4; mt++)
#pragma unroll
                for (int nt = 0; nt < 4; nt++) {
                    MMA_BF16(c[mt][nt], ah[mt], bh[nt]);
                    MMA_BF16(c[mt][nt], ah[mt], bl[nt]);
                    MMA_BF16(c[mt][nt], al[mt], bh[nt]);
                }
        }
        __syncthreads();
    }

    // Epilogue: direct global stores from fragments
    const int g = lane >> 2;
    const int cc2 = lane & 3;
#pragma unroll
    for (int mt = 0; mt < 4; mt++) {
        int row0 = bm + wm * 64 + mt * 16 + g;
#pragma unroll
        for (int nt = 0; nt < 4; nt++) {
            int col = bn + wn * 32 + nt * 8 + 2 * cc2;
            *(float2*)&C[(size_t)row0 * Ndim + col] =
                make_float2(c[mt][nt][0], c[mt][nt][1]);
            *(float2*)&C[(size_t)(row0 + 8) * Ndim + col] =
                make_float2(c[mt][nt][2], c[mt][nt][3]);
        }
    }
#undef LOAD_TILE
}

// ---------------------------------------------------------------------------
// RoPE over q (32 heads) and k (8 heads), interleaved-pair convention.
// ---------------------------------------------------------------------------
__global__ void rope_kernel(const int* __restrict__ pos_ids)
{
    const int half = HDn / 2;
    int idx = blockIdx.x * blockDim.x + threadIdx.x;
    const int total = MROWS * (HQn + HKVn) * half;
    if (idx >= total) return;

    int j = idx % half;
    int rest = idx / half;
    int h = rest % (HQn + HKVn);
    int row = rest / (HQn + HKVn);
    int l = row % Ln;

    float pos = (float)pos_ids[l];
    float inv = expf(-logf(10000.0f) * ((float)j / (float)half));
    float ang = pos * inv;
    float c = cosf(ang);
    float s = sinf(ang);

    float* base;
    if (h < HQn) base = &g_q[(size_t)row * Dn + h * HDn];
    else         base = &g_k[(size_t)row * NKV + (h - HQn) * HDn];

    float x1 = base[2 * j];
    float x2 = base[2 * j + 1];
    base[2 * j]     = x1 * c - x2 * s;
    base[2 * j + 1] = x1 * s + x2 * c;
}

// ---------------------------------------------------------------------------
// Flash-style fp32 attention (unchanged from R1, which passed).
// ---------------------------------------------------------------------------
#define QS_STRIDE 65
#define VS_STRIDE 68
#define ATTN_SMEM_FLOATS (64 * QS_STRIDE * 2 + 64 * VS_STRIDE)
#define ATTN_SMEM_BYTES (ATTN_SMEM_FLOATS * 4)

__global__ __launch_bounds__(256) void attn_kernel(float* __restrict__ o)
{
    extern __shared__ float sm[];
    float* qs = sm;
    float* ks = sm + 64 * QS_STRIDE;
    float* vs = sm + 2 * 64 * QS_STRIDE;

    const int qt = blockIdx.x;
    const int h  = blockIdx.y;
    const int b  = blockIdx.z;
    const int l0 = qt * 64;
    const int kh = h >> 2;

    const int tid = threadIdx.x;
    const int tx = tid & 15;
    const int ty = tid >> 4;

#pragma unroll
    for (int it = 0; it < 4; it++) {
        int idx = tid + it * 256;
        int r = idx >> 4, c4 = idx & 15;
        float4 qv = *(const float4*)&g_q[(size_t)(b * Ln + l0 + r) * Dn + h * HDn + c4 * 4];
        qs[(c4 * 4 + 0) * QS_STRIDE + r] = qv.x;
        qs[(c4 * 4 + 1) * QS_STRIDE + r] = qv.y;
        qs[(c4 * 4 + 2) * QS_STRIDE + r] = qv.z;
        qs[(c4 * 4 + 3) * QS_STRIDE + r] = qv.w;
    }

    float acc[4][4];
    float rm[4], rs[4];
#pragma unroll
    for (int i = 0; i < 4; i++) {
        rm[i] = -1e30f;
        rs[i] = 0.0f;
#pragma unroll
        for (int j = 0; j < 4; j++) acc[i][j] = 0.0f;
    }

    int row_maxm[4];
#pragma unroll
    for (int i = 0; i < 4; i++) {
        int l = l0 + 4 * ty + i;
        row_maxm[i] = (l / TPF) * TPF + TPF - 1;
    }
    int maxm = ((l0 + 63) / TPF) * TPF + TPF - 1;
    if (maxm > Ln - 1) maxm = Ln - 1;
    const int nkt = maxm / 64 + 1;
    const int q0fid = l0 / TPF;

    for (int kt = 0; kt < nkt; kt++) {
        const int m0 = kt * 64;
        __syncthreads();
#pragma unroll
        for (int it = 0; it < 4; it++) {
            int idx = tid + it * 256;
            int r = idx >> 4, c4 = idx & 15;
            size_t grow = (size_t)(b * Ln + m0 + r) * NKV + kh * HDn + c4 * 4;
            float4 kv = *(const float4*)&g_k[grow];
            ks[(c4 * 4 + 0) * QS_STRIDE + r] = kv.x;
            ks[(c4 * 4 + 1) * QS_STRIDE + r] = kv.y;
            ks[(c4 * 4 + 2) * QS_STRIDE + r] = kv.z;
            ks[(c4 * 4 + 3) * QS_STRIDE + r] = kv.w;
            float4 vv = *(const float4*)&g_v[grow];
            *(float4*)&vs[r * VS_STRIDE + c4 * 4] = vv;
        }
        __syncthreads();

        float s[4][4];
#pragma unroll
        for (int i = 0; i < 4; i++)
#pragma unroll
            for (int j = 0; j < 4; j++) s[i][j] = 0.0f;
#pragma unroll 8
        for (int d = 0; d < 64; d++) {
            float qv[4], kv[4];
#pragma unroll
            for (int i = 0; i < 4; i++) qv[i] = qs[d * QS_STRIDE + 4 * ty + i];
#pragma unroll
            for (int j = 0; j < 4; j++) kv[j] = ks[d * QS_STRIDE + 4 * tx + j];
#pragma unroll
            for (int i = 0; i < 4; i++)
#pragma unroll
                for (int j = 0; j < 4; j++)
                    s[i][j] = fmaf(qv[i], kv[j], s[i][j]);
        }

        const bool full = ((m0 + 63) / TPF) <= q0fid;
        const float scale = 0.125f;
#pragma unroll
        for (int i = 0; i < 4; i++)
#pragma unroll
            for (int j = 0; j < 4; j++) {
                s[i][j] *= scale;
                if (!full) {
                    int m = m0 + 4 * tx + j;
                    if (m > row_maxm[i]) s[i][j] = -1e30f;
                }
            }

        float p[4][4];
#pragma unroll
        for (int i = 0; i < 4; i++) {
            float tm = s[i][0];
#pragma unroll
            for (int j = 1; j < 4; j++) tm = fmaxf(tm, s[i][j]);
#pragma unroll
            for (int off = 8; off >= 1; off >>= 1)
                tm = fmaxf(tm, __shfl_xor_sync(0xffffffffu, tm, off));
            float nm = fmaxf(rm[i], tm);
            float fac = expf(rm[i] - nm);
            float ls = 0.0f;
#pragma unroll
            for (int j = 0; j < 4; j++) {
                p[i][j] = expf(s[i][j] - nm);
                ls += p[i][j];
            }
#pragma unroll
            for (int off = 8; off >= 1; off >>= 1)
                ls += __shfl_xor_sync(0xffffffffu, ls, off);
            rs[i] = rs[i] * fac + ls;
            rm[i] = nm;
#pragma unroll
            for (int j = 0; j < 4; j++) acc[i][j] *= fac;
        }

        __syncthreads();
#pragma unroll
        for (int i = 0; i < 4; i++)
#pragma unroll
            for (int j = 0; j < 4; j++)
                ks[(4 * ty + i) * QS_STRIDE + 4 * tx + j] = p[i][j];
        __syncthreads();

#pragma unroll 8
        for (int m = 0; m < 64; m++) {
            float pv[4], vv[4];
#pragma unroll
            for (int i = 0; i < 4; i++) pv[i] = ks[(4 * ty + i) * QS_STRIDE + m];
#pragma unroll
            for (int j = 0; j < 4; j++) vv[j] = vs[m * VS_STRIDE + 4 * tx + j];
#pragma unroll
            for (int i = 0; i < 4; i++)
#pragma unroll
                for (int j = 0; j < 4; j++)
                    acc[i][j] = fmaf(pv[i], vv[j], acc[i][j]);
        }
    }

#pragma unroll
    for (int i = 0; i < 4; i++) {
        float inv = 1.0f / rs[i];
        float4 o4 = make_float4(acc[i][0] * inv, acc[i][1] * inv,
                                acc[i][2] * inv, acc[i][3] * inv);
        *(float4*)&o[(size_t)(b * Ln + l0 + 4 * ty + i) * Dn + h * HDn + 4 * tx] = o4;
    }
}

// ---------------------------------------------------------------------------
// Launch
// ---------------------------------------------------------------------------
extern "C" void kernel_launch(void* const* d_in, const int* in_sizes, int n_in,
                              void* d_out, int out_size)
{
    const float* x   = (const float*)d_in[0];
    const float* wq  = (const float*)d_in[1];
    const float* wk  = (const float*)d_in[2];
    const float* wv  = (const float*)d_in[3];
    const float* wo  = (const float*)d_in[4];
    const int*   pos = (const int*)d_in[5];
    float* out = (float*)d_out;

    float *q, *k, *v, *attn;
    cudaGetSymbolAddress((void**)&q,    g_q);
    cudaGetSymbolAddress((void**)&k,    g_k);
    cudaGetSymbolAddress((void**)&v,    g_v);
    cudaGetSymbolAddress((void**)&attn, g_attn);

    __nv_bfloat16 *xh, *xl, *wqh, *wql, *wkh, *wkl, *wvh, *wvl, *woh, *wol, *ah, *al;
    cudaGetSymbolAddress((void**)&xh,  g_xh);  cudaGetSymbolAddress((void**)&xl,  g_xl);
    cudaGetSymbolAddress((void**)&wqh, g_wqh); cudaGetSymbolAddress((void**)&wql, g_wql);
    cudaGetSymbolAddress((void**)&wkh, g_wkh); cudaGetSymbolAddress((void**)&wkl, g_wkl);
    cudaGetSymbolAddress((void**)&wvh, g_wvh); cudaGetSymbolAddress((void**)&wvl, g_wvl);
    cudaGetSymbolAddress((void**)&woh, g_woh); cudaGetSymbolAddress((void**)&wol, g_wol);
    cudaGetSymbolAddress((void**)&ah,  g_ah);  cudaGetSymbolAddress((void**)&al,  g_al);

    cudaFuncSetAttribute((const void*)attn_kernel,
                         cudaFuncAttributeMaxDynamicSharedMemorySize,
                         ATTN_SMEM_BYTES);
    cudaFuncSetAttribute((const void*)gemm_bf16x3_kernel,
                         cudaFuncAttributeMaxDynamicSharedMemorySize,
                         GEMM_SMEM_BYTES);

    // Split inputs to bf16 hi/lo
    {
        int n4;
        n4 = MROWS * Dn / 4;  split_kernel<<<(n4 + 255) / 256, 256>>>(x,  xh,  xl,  n4);
        n4 = Dn * Dn / 4;     split_kernel<<<(n4 + 255) / 256, 256>>>(wq, wqh, wql, n4);
        n4 = Dn * NKV / 4;    split_kernel<<<(n4 + 255) / 256, 256>>>(wk, wkh, wkl, n4);
        n4 = Dn * NKV / 4;    split_kernel<<<(n4 + 255) / 256, 256>>>(wv, wvh, wvl, n4);
        n4 = Dn * Dn / 4;     split_kernel<<<(n4 + 255) / 256, 256>>>(wo, woh, wol, n4);
    }

    dim3 gq(Dn / 128, MROWS / 128);     // 16 x 28
    dim3 gkv(NKV / 128, MROWS / 128);   // 4 x 28

    gemm_bf16x3_kernel<<<gq, 256, GEMM_SMEM_BYTES>>>(xh, xl, wqh, wql, q, Dn, Dn);
    gemm_bf16x3_kernel<<<gkv, 256, GEMM_SMEM_BYTES>>>(xh, xl, wkh, wkl, k, NKV, Dn);
    gemm_bf16x3_kernel<<<gkv, 256, GEMM_SMEM_BYTES>>>(xh, xl, wvh, wvl, v, NKV, Dn);

    int total = MROWS * (HQn + HKVn) * (HDn / 2);
    rope_kernel<<<(total + 255) / 256, 256>>>(pos);

    dim3 ga(Ln / 64, HQn, Bn);
    attn_kernel<<<ga, 256, ATTN_SMEM_BYTES>>>(attn);

    {
        int n4 = MROWS * Dn / 4;
        split_kernel<<<(n4 + 255) / 256, 256>>>(attn, ah, al, n4);
    }
    gemm_bf16x3_kernel<<<gq, 256, GEMM_SMEM_BYTES>>>(ah, al, woh, wol, out, Dn, Dn);
}

// round 5
// speedup vs baseline: 3.9740x; 1.4840x over previous
#include <cuda_runtime.h>
#include <cuda_bf16.h>
#include <cstdint>

// Problem constants
#define Bn 4
#define Ln 896
#define Dn 2048
#define HQn 32
#define HKVn 8
#define HDn 64
#define TPF 7
#define MROWS (Bn * Ln)      // 3584
#define NKV (HKVn * HDn)     // 512
#define LOG2E 1.4426950408889634f

// Scratch (no allocation allowed -> device globals)
__device__ float g_q[MROWS * Dn];
__device__ float g_k[MROWS * NKV];
__device__ float g_v[MROWS * NKV];

// Split bf16 operand buffers (GEMM inputs)
__device__ __nv_bfloat16 g_xh[MROWS * Dn],  g_xl[MROWS * Dn];
__device__ __nv_bfloat16 g_wqh[Dn * Dn],    g_wql[Dn * Dn];
__device__ __nv_bfloat16 g_wkh[Dn * NKV],   g_wkl[Dn * NKV];
__device__ __nv_bfloat16 g_wvh[Dn * NKV],   g_wvl[Dn * NKV];
__device__ __nv_bfloat16 g_woh[Dn * Dn],    g_wol[Dn * Dn];
// Attention operands / outputs (bf16 hi/lo)
__device__ __nv_bfloat16 g_qh[MROWS * Dn],  g_ql[MROWS * Dn];
__device__ __nv_bfloat16 g_kth[MROWS * NKV], g_ktl[MROWS * NKV]; // [b][kvh][d][L]
__device__ __nv_bfloat16 g_vhh[MROWS * NKV], g_vll[MROWS * NKV];
__device__ __nv_bfloat16 g_ah[MROWS * Dn],  g_al[MROWS * Dn];

__device__ __forceinline__ uint32_t smem_u32(const void* p) {
    uint32_t a;
    asm("{ .reg .u64 t; cvta.to.shared.u64 t, %1; cvt.u32.u64 %0, t; }"
        : "=r"(a) : "l"(p));
    return a;
}

#define CP_ASYNC16(dst, src) \
    asm volatile("cp.async.cg.shared.global [%0], [%1], 16;" :: "r"(dst), "l"(src))
#define CP_COMMIT() asm volatile("cp.async.commit_group;" ::: "memory")
#define CP_WAIT1()  asm volatile("cp.async.wait_group 1;" ::: "memory")
#define CP_WAIT0()  asm volatile("cp.async.wait_group 0;" ::: "memory")

#define MMA_BF16(cc, a, b0, b1) \
    asm volatile( \
        "mma.sync.aligned.m16n8k16.row.col.f32.bf16.bf16.f32 " \
        "{%0,%1,%2,%3}, {%4,%5,%6,%7}, {%8,%9}, {%0,%1,%2,%3};" \
        : "+f"((cc)[0]), "+f"((cc)[1]), "+f"((cc)[2]), "+f"((cc)[3]) \
        : "r"((a)[0]), "r"((a)[1]), "r"((a)[2]), "r"((a)[3]), \
          "r"(b0), "r"(b1))

#define LDSM4(r, addr) \
    asm volatile("ldmatrix.sync.aligned.m8n8.x4.shared.b16 {%0,%1,%2,%3}, [%4];" \
        : "=r"((r)[0]), "=r"((r)[1]), "=r"((r)[2]), "=r"((r)[3]) : "r"(addr))
#define LDSM4T(r0, r1, r2, r3, addr) \
    asm volatile("ldmatrix.sync.aligned.m8n8.x4.trans.shared.b16 {%0,%1,%2,%3}, [%4];" \
        : "=r"(r0), "=r"(r1), "=r"(r2), "=r"(r3) : "r"(addr))

// Fast exp2 on the FMA pipe (no MUFU). |rel err| ~2.4e-6 over full range.
__device__ __forceinline__ float exp2p(float t) {
    t = fmaxf(t, -119.0f);
    float z = t + 12582912.0f;           // round-to-nearest-int via magic number
    float f = t - (z - 12582912.0f);     // f in [-0.5, 0.5]
    int iv = __float_as_int(z);
    float p =            1.3333558e-3f;
    p = fmaf(p, f, 9.6181291e-3f);
    p = fmaf(p, f, 5.5504109e-2f);
    p = fmaf(p, f, 2.4022651e-1f);
    p = fmaf(p, f, 6.9314718e-1f);
    p = fmaf(p, f, 1.0f);
    return __int_as_float(__float_as_int(p) + (iv << 23));
}

// Pack 2 floats -> bf16x2 hi + bf16x2 lo residual
__device__ __forceinline__ void pack_hl(float v0, float v1, uint32_t& h, uint32_t& l) {
    uint32_t hh;
    asm("cvt.rn.bf16x2.f32 %0, %1, %2;" : "=r"(hh) : "f"(v1), "f"(v0));
    float h0 = __int_as_float(hh << 16);
    float h1 = __int_as_float(hh & 0xFFFF0000u);
    float l0 = v0 - h0, l1 = v1 - h1;
    asm("cvt.rn.bf16x2.f32 %0, %1, %2;" : "=r"(l) : "f"(l1), "f"(l0));
    h = hh;
}

// ---------------------------------------------------------------------------
// Split fp32 -> (bf16 hi, bf16 lo). n must be divisible by 4.
// ---------------------------------------------------------------------------
__global__ void split_kernel(const float* __restrict__ src,
                             __nv_bfloat16* __restrict__ hi,
                             __nv_bfloat16* __restrict__ lo, int n4)
{
    int i = blockIdx.x * blockDim.x + threadIdx.x;
    if (i >= n4) return;
    float4 v = ((const float4*)src)[i];
    uint32_t h0, l0, h1, l1;
    pack_hl(v.x, v.y, h0, l0);
    pack_hl(v.z, v.w, h1, l1);
    ((uint32_t*)hi)[2 * i] = h0;  ((uint32_t*)hi)[2 * i + 1] = h1;
    ((uint32_t*)lo)[2 * i] = l0;  ((uint32_t*)lo)[2 * i + 1] = l1;
}

// ---------------------------------------------------------------------------
// Split-bf16 GEMM (unchanged from R4): C = (Ah+Al)(Bh+Bl), 3 terms.
// ---------------------------------------------------------------------------
#define STAGE_BYTES (16384 + 8192 + 8192)
#define GEMM_STAGES 3
#define GEMM_SMEM_BYTES (GEMM_STAGES * STAGE_BYTES)

__global__ __launch_bounds__(256) void gemm_bf16x3_kernel(
    const __nv_bfloat16* __restrict__ Ah, const __nv_bfloat16* __restrict__ Al,
    const __nv_bfloat16* __restrict__ Bh, const __nv_bfloat16* __restrict__ Bl,
    float* __restrict__ C, int Ndim, int Kdim)
{
    extern __shared__ char smraw[];
    const uint32_t smb = smem_u32(smraw);
    const int tid = threadIdx.x;
    const int wid = tid >> 5;
    const int lane = tid & 31;
    const int bm = blockIdx.y * 128;
    const int bn = blockIdx.x * 128;
    const int wm = wid >> 2;
    const int wn = wid & 3;

    float c[4][4][4];
#pragma unroll
    for (int mt = 0; mt < 4; mt++)
#pragma unroll
        for (int nt = 0; nt < 4; nt++)
#pragma unroll
            for (int r = 0; r < 4; r++) c[mt][nt][r] = 0.0f;

    const int nk = Kdim / 32;

#define LOAD_TILE(s, k0) do { \
        uint32_t baseA = smb + (s) * STAGE_BYTES; \
        uint32_t baseBh = baseA + 16384; \
        uint32_t baseBl = baseBh + 8192; \
        const int ca = tid & 7; \
        _Pragma("unroll") \
        for (int it = 0; it < 4; it++) { \
            int row = (tid >> 3) + it * 32; \
            const __nv_bfloat16* src = (ca < 4) \
                ? Ah + (size_t)(bm + row) * Kdim + (k0) + ca * 8 \
                : Al + (size_t)(bm + row) * Kdim + (k0) + (ca - 4) * 8; \
            CP_ASYNC16(baseA + row * 128 + ((ca ^ (row & 7)) << 4), src); \
        } \
        const int cb = tid & 15; \
        _Pragma("unroll") \
        for (int it = 0; it < 2; it++) { \
            int kr = (tid >> 4) + it * 16; \
            uint32_t off = kr * 256 + ((cb ^ (kr & 7)) << 4); \
            CP_ASYNC16(baseBh + off, Bh + (size_t)((k0) + kr) * Ndim + bn + cb * 8); \
            CP_ASYNC16(baseBl + off, Bl + (size_t)((k0) + kr) * Ndim + bn + cb * 8); \
        } \
    } while (0)

    LOAD_TILE(0, 0);
    CP_COMMIT();
    LOAD_TILE(1, 32);
    CP_COMMIT();

    const int a_row_l = (lane & 15);
    const int a_inner = (lane >> 4) & 1;
    const int b_krow_l = ((lane >> 3) & 1) * 8 + (lane & 7);
    const int b_nch = (lane >> 4) & 1;

    for (int i = 0; i < nk; i++) {
        CP_WAIT1();
        __syncthreads();

        if (i + 2 < nk) {
            int s = (i + 2) % GEMM_STAGES;
            LOAD_TILE(s, (i + 2) * 32);
        }
        CP_COMMIT();

        const int buf = i % GEMM_STAGES;
        const uint32_t smA  = smb + buf * STAGE_BYTES;
        const uint32_t smBh = smA + 16384;
        const uint32_t smBl = smBh + 8192;

#pragma unroll
        for (int kk = 0; kk < 2; kk++) {
            uint32_t ah[4][4], al[4][4];
#pragma unroll
            for (int mt = 0; mt < 4; mt++) {
                int row = wm * 64 + mt * 16 + a_row_l;
                int lch = kk * 2 + a_inner;
                uint32_t offh = smA + row * 128 + (((lch) ^ (row & 7)) << 4);
                uint32_t offl = smA + row * 128 + (((lch + 4) ^ (row & 7)) << 4);
                LDSM4(ah[mt], offh);
                LDSM4(al[mt], offl);
            }
            uint32_t bh[4][2], bl[4][2];
#pragma unroll
            for (int p = 0; p < 2; p++) {
                int kr = kk * 16 + b_krow_l;
                int nchunk = wn * 4 + p * 2 + b_nch;
                uint32_t off = kr * 256 + ((nchunk ^ (kr & 7)) << 4);
                uint32_t r0, r1, r2, r3;
                LDSM4T(r0, r1, r2, r3, smBh + off);
                bh[2 * p][0] = r0; bh[2 * p][1] = r1;
                bh[2 * p + 1][0] = r2; bh[2 * p + 1][1] = r3;
                LDSM4T(r0, r1, r2, r3, smBl + off);
                bl[2 * p][0] = r0; bl[2 * p][1] = r1;
                bl[2 * p + 1][0] = r2; bl[2 * p + 1][1] = r3;
            }
#pragma unroll
            for (int mt = 0; mt < 4; mt++)
#pragma unroll
                for (int nt = 0; nt < 4; nt++) {
                    MMA_BF16(c[mt][nt], ah[mt], bh[nt][0], bh[nt][1]);
                    MMA_BF16(c[mt][nt], ah[mt], bl[nt][0], bl[nt][1]);
                    MMA_BF16(c[mt][nt], al[mt], bh[nt][0], bh[nt][1]);
                }
        }
        __syncthreads();
    }

    const int g = lane >> 2;
    const int cc2 = lane & 3;
#pragma unroll
    for (int mt = 0; mt < 4; mt++) {
        int row0 = bm + wm * 64 + mt * 16 + g;
#pragma unroll
        for (int nt = 0; nt < 4; nt++) {
            int col = bn + wn * 32 + nt * 8 + 2 * cc2;
            *(float2*)&C[(size_t)row0 * Ndim + col] =
                make_float2(c[mt][nt][0], c[mt][nt][1]);
            *(float2*)&C[(size_t)(row0 + 8) * Ndim + col] =
                make_float2(c[mt][nt][2], c[mt][nt][3]);
        }
    }
#undef LOAD_TILE
}

// ---------------------------------------------------------------------------
// RoPE+split for Q: reads fp32 g_q, writes bf16 hi/lo row-major.
// One thread per (row, head, pair j).
// ---------------------------------------------------------------------------
__global__ void rope_split_q(const int* __restrict__ pos_ids)
{
    int idx = blockIdx.x * blockDim.x + threadIdx.x;
    if (idx >= MROWS * HQn * 32) return;
    int j = idx & 31;
    int h = (idx >> 5) & 31;
    int row = idx >> 10;
    int l = row % Ln;

    float pos = (float)pos_ids[l];
    float inv = expf(-logf(10000.0f) * ((float)j / 32.0f));
    float ang = pos * inv;
    float cth = cosf(ang), sth = sinf(ang);

    const float* bp = &g_q[(size_t)row * Dn + h * HDn + 2 * j];
    float x1 = bp[0], x2 = bp[1];
    float y1 = x1 * cth - x2 * sth;
    float y2 = x1 * sth + x2 * cth;
    uint32_t hh, ll;
    pack_hl(y1, y2, hh, ll);
    size_t o = ((size_t)row * Dn + h * HDn) / 2 + j;
    ((uint32_t*)g_qh)[o] = hh;
    ((uint32_t*)g_ql)[o] = ll;
}

// ---------------------------------------------------------------------------
// RoPE+split+transpose for K: reads fp32 g_k [row][kvh*64+d],
// writes bf16 hi/lo transposed: [b][kvh][d][L].
// grid (Ln/128, HKVn*32, Bn), block 128. Thread = (l | kvh,j | b).
// ---------------------------------------------------------------------------
__global__ void rope_split_kT(const int* __restrict__ pos_ids)
{
    int l = blockIdx.x * 128 + threadIdx.x;
    int kvh = blockIdx.y >> 5;
    int j = blockIdx.y & 31;
    int b = blockIdx.z;

    float pos = (float)pos_ids[l];
    float inv = expf(-logf(10000.0f) * ((float)j / 32.0f));
    float ang = pos * inv;
    float cth = cosf(ang), sth = sinf(ang);

    const float* bp = &g_k[(size_t)(b * Ln + l) * NKV + kvh * HDn + 2 * j];
    float x1 = bp[0], x2 = bp[1];
    float y1 = x1 * cth - x2 * sth;
    float y2 = x1 * sth + x2 * cth;

    __nv_bfloat16 h1 = __float2bfloat16_rn(y1);
    __nv_bfloat16 h2 = __float2bfloat16_rn(y2);
    __nv_bfloat16 l1 = __float2bfloat16_rn(y1 - __bfloat162float(h1));
    __nv_bfloat16 l2 = __float2bfloat16_rn(y2 - __bfloat162float(h2));

    size_t base = ((size_t)(b * HKVn + kvh) * HDn + 2 * j) * Ln + l;
    g_kth[base] = h1;       g_kth[base + Ln] = h2;
    g_ktl[base] = l1;       g_ktl[base + Ln] = l2;
}

// ---------------------------------------------------------------------------
// Tensor-core flash attention.
// Block = (q-tile 64, head, batch), 128 threads (4 warps, 16 q-rows each).
// S = Q K^T via bf16x3 mma; softmax with poly-exp2 on FMA pipe;
// P kept in registers (C-fragment == A-fragment repack); O = P V via bf16x3.
// Writes split bf16 hi/lo output directly for the wo GEMM.
// SMEM: Qh|Ql 16KB + 2 x (Kh|Kl|Vh|Vl 32KB) = 80KB.
// ---------------------------------------------------------------------------
#define ATT_SMEM_BYTES (16384 + 2 * 32768)

__global__ __launch_bounds__(128) void attn_kernel()
{
    extern __shared__ char smraw[];
    const uint32_t smb = smem_u32(smraw);
    const int tid = threadIdx.x;
    const int wid = tid >> 5;
    const int lane = tid & 31;
    const int qt = blockIdx.x, h = blockIdx.y, b = blockIdx.z;
    const int l0 = qt * 64;
    const int kh = h >> 2;

    const uint32_t QH = smb, QL = smb + 8192;

    // Q load (grouped with tile 0)
#pragma unroll
    for (int it = 0; it < 4; it++) {
        int idx = tid + it * 128;
        int row = idx >> 3, c = idx & 7;
        uint32_t off = row * 128 + ((c ^ (row & 7)) << 4);
        size_t g = (size_t)(b * Ln + l0 + row) * Dn + h * HDn + c * 8;
        CP_ASYNC16(QH + off, g_qh + g);
        CP_ASYNC16(QL + off, g_ql + g);
    }

#define LOAD_KV(p, m0_) do { \
        uint32_t KB = smb + 16384 + (p) * 32768; \
        _Pragma("unroll") \
        for (int it = 0; it < 4; it++) { \
            int idx = tid + it * 128; \
            int row = idx >> 3, c = idx & 7; \
            uint32_t off = row * 128 + (uint32_t)((c ^ (row & 7)) << 4); \
            size_t gk = ((size_t)(b * HKVn + kh) * HDn + row) * Ln + (m0_) + c * 8; \
            size_t gv = (size_t)(b * Ln + (m0_) + row) * NKV + kh * HDn + c * 8; \
            CP_ASYNC16(KB + off,         g_kth + gk); \
            CP_ASYNC16(KB + 8192 + off,  g_ktl + gk); \
            CP_ASYNC16(KB + 16384 + off, g_vhh + gv); \
            CP_ASYNC16(KB + 24576 + off, g_vll + gv); \
        } \
    } while (0)

    int maxm = ((l0 + 63) / TPF) * TPF + TPF - 1;
    if (maxm > Ln - 1) maxm = Ln - 1;
    const int nkt = maxm / 64 + 1;

    LOAD_KV(0, 0);
    CP_COMMIT();

    // per-lane constants
    const int q4 = lane & 3;
    const int rr = lane >> 2;
    const int aRow = wid * 16 + (lane & 15);
    const int aSel = (lane >> 4) & 1;
    const int bKr = ((lane >> 3) & 1) * 8 + (lane & 7);
    const int bNch = (lane >> 4) & 1;
    const int grow0 = l0 + wid * 16 + rr;
    const int grow1 = grow0 + 8;
    const int rowmax0 = (grow0 / TPF) * TPF + TPF - 1;
    const int rowmax1 = (grow1 / TPF) * TPF + TPF - 1;
    const int l0fid = l0 / TPF;
    const float K1 = 0.125f * LOG2E;

    float o[8][4];
#pragma unroll
    for (int nt = 0; nt < 8; nt++)
#pragma unroll
        for (int r = 0; r < 4; r++) o[nt][r] = 0.0f;
    float rm0 = -1e30f, rm1 = -1e30f, rs0 = 0.0f, rs1 = 0.0f;

    for (int i = 0; i < nkt; i++) {
        if (i + 1 < nkt) {
            LOAD_KV((i + 1) & 1, (i + 1) * 64);
            CP_COMMIT();
            CP_WAIT1();
        } else {
            CP_WAIT0();
        }
        __syncthreads();

        const uint32_t KB = smb + 16384 + (i & 1) * 32768;
        const uint32_t KHs = KB, KLs = KB + 8192;
        const uint32_t VHs = KB + 16384, VLs = KB + 24576;
        const int m0 = i * 64;

        // ---- S = Q K^T (3-term bf16) ----
        float s[8][4];
#pragma unroll
        for (int nt = 0; nt < 8; nt++)
#pragma unroll
            for (int r = 0; r < 4; r++) s[nt][r] = 0.0f;

#pragma unroll
        for (int kb = 0; kb < 4; kb++) {
            uint32_t aH[4], aL[4];
            {
                int ch = kb * 2 + aSel;
                uint32_t off = aRow * 128 + ((ch ^ (aRow & 7)) << 4);
                LDSM4(aH, QH + off);
                LDSM4(aL, QL + off);
            }
#pragma unroll
            for (int np = 0; np < 4; np++) {
                int kr = kb * 16 + bKr;
                int nch = np * 2 + bNch;
                uint32_t off = kr * 128 + ((nch ^ (kr & 7)) << 4);
                uint32_t h0, h1, h2, h3, lo0, lo1, lo2, lo3;
                LDSM4T(h0, h1, h2, h3, KHs + off);
                LDSM4T(lo0, lo1, lo2, lo3, KLs + off);
                MMA_BF16(s[2 * np], aH, h0, h1);
                MMA_BF16(s[2 * np], aH, lo0, lo1);
                MMA_BF16(s[2 * np], aL, h0, h1);
                MMA_BF16(s[2 * np + 1], aH, h2, h3);
                MMA_BF16(s[2 * np + 1], aH, lo2, lo3);
                MMA_BF16(s[2 * np + 1], aL, h2, h3);
            }
        }

        // ---- mask ----
        const bool full = ((m0 + 63) / TPF) <= l0fid;
        if (!full) {
#pragma unroll
            for (int nt = 0; nt < 8; nt++) {
                int colb = m0 + nt * 8 + 2 * q4;
                if (colb > rowmax0)     s[nt][0] = -1e30f;
                if (colb + 1 > rowmax0) s[nt][1] = -1e30f;
                if (colb > rowmax1)     s[nt][2] = -1e30f;
                if (colb + 1 > rowmax1) s[nt][3] = -1e30f;
            }
        }

        // ---- online softmax (rows r and r+8, quad shuffle reductions) ----
        float mx0 = -1e30f, mx1 = -1e30f;
#pragma unroll
        for (int nt = 0; nt < 8; nt++) {
            mx0 = fmaxf(mx0, fmaxf(s[nt][0], s[nt][1]));
            mx1 = fmaxf(mx1, fmaxf(s[nt][2], s[nt][3]));
        }
        mx0 = fmaxf(mx0, __shfl_xor_sync(0xffffffffu, mx0, 1));
        mx0 = fmaxf(mx0, __shfl_xor_sync(0xffffffffu, mx0, 2));
        mx1 = fmaxf(mx1, __shfl_xor_sync(0xffffffffu, mx1, 1));
        mx1 = fmaxf(mx1, __shfl_xor_sync(0xffffffffu, mx1, 2));

        float nm0 = fmaxf(rm0, 0.125f * mx0);
        float nm1 = fmaxf(rm1, 0.125f * mx1);
        float fac0 = exp2p((rm0 - nm0) * LOG2E);
        float fac1 = exp2p((rm1 - nm1) * LOG2E);
        float em0 = nm0 * LOG2E, em1 = nm1 * LOG2E;

        float ls0 = 0.0f, ls1 = 0.0f;
#pragma unroll
        for (int nt = 0; nt < 8; nt++) {
            s[nt][0] = exp2p(fmaf(s[nt][0], K1, -em0));
            s[nt][1] = exp2p(fmaf(s[nt][1], K1, -em0));
            s[nt][2] = exp2p(fmaf(s[nt][2], K1, -em1));
            s[nt][3] = exp2p(fmaf(s[nt][3], K1, -em1));
            ls0 += s[nt][0] + s[nt][1];
            ls1 += s[nt][2] + s[nt][3];
        }
        ls0 += __shfl_xor_sync(0xffffffffu, ls0, 1);
        ls0 += __shfl_xor_sync(0xffffffffu, ls0, 2);
        ls1 += __shfl_xor_sync(0xffffffffu, ls1, 1);
        ls1 += __shfl_xor_sync(0xffffffffu, ls1, 2);

        rs0 = rs0 * fac0 + ls0;  rm0 = nm0;
        rs1 = rs1 * fac1 + ls1;  rm1 = nm1;

#pragma unroll
        for (int nt = 0; nt < 8; nt++) {
            o[nt][0] *= fac0;  o[nt][1] *= fac0;
            o[nt][2] *= fac1;  o[nt][3] *= fac1;
        }

        // ---- pack P into A fragments (hi + lo) ----
        uint32_t ph[4][4], pl[4][4];
#pragma unroll
        for (int kb = 0; kb < 4; kb++) {
            pack_hl(s[2 * kb][0],     s[2 * kb][1],     ph[kb][0], pl[kb][0]);
            pack_hl(s[2 * kb][2],     s[2 * kb][3],     ph[kb][1], pl[kb][1]);
            pack_hl(s[2 * kb + 1][0], s[2 * kb + 1][1], ph[kb][2], pl[kb][2]);
            pack_hl(s[2 * kb + 1][2], s[2 * kb + 1][3], ph[kb][3], pl[kb][3]);
        }

        // ---- O += P V (3-term bf16) ----
#pragma unroll
        for (int kb = 0; kb < 4; kb++) {
#pragma unroll
            for (int np = 0; np < 4; np++) {
                int kr = kb * 16 + bKr;
                int nch = np * 2 + bNch;
                uint32_t off = kr * 128 + ((nch ^ (kr & 7)) << 4);
                uint32_t h0, h1, h2, h3, lo0, lo1, lo2, lo3;
                LDSM4T(h0, h1, h2, h3, VHs + off);
                LDSM4T(lo0, lo1, lo2, lo3, VLs + off);
                MMA_BF16(o[2 * np], ph[kb], h0, h1);
                MMA_BF16(o[2 * np], pl[kb], h0, h1);
                MMA_BF16(o[2 * np], ph[kb], lo0, lo1);
                MMA_BF16(o[2 * np + 1], ph[kb], h2, h3);
                MMA_BF16(o[2 * np + 1], pl[kb], h2, h3);
                MMA_BF16(o[2 * np + 1], ph[kb], lo2, lo3);
            }
        }
        __syncthreads();
    }

    // ---- epilogue: normalize, split to bf16 hi/lo, store ----
    float inv0 = 1.0f / rs0, inv1 = 1.0f / rs1;
#pragma unroll
    for (int nt = 0; nt < 8; nt++) {
        uint32_t hh, ll;
        size_t a0 = (size_t)(b * Ln + grow0) * Dn + h * HDn + nt * 8 + 2 * q4;
        pack_hl(o[nt][0] * inv0, o[nt][1] * inv0, hh, ll);
        *(uint32_t*)(g_ah + a0) = hh;
        *(uint32_t*)(g_al + a0) = ll;
        size_t a1 = (size_t)(b * Ln + grow1) * Dn + h * HDn + nt * 8 + 2 * q4;
        pack_hl(o[nt][2] * inv1, o[nt][3] * inv1, hh, ll);
        *(uint32_t*)(g_ah + a1) = hh;
        *(uint32_t*)(g_al + a1) = ll;
    }
#undef LOAD_KV
}

// ---------------------------------------------------------------------------
// Launch
// ---------------------------------------------------------------------------
extern "C" void kernel_launch(void* const* d_in, const int* in_sizes, int n_in,
                              void* d_out, int out_size)
{
    const float* x   = (const float*)d_in[0];
    const float* wq  = (const float*)d_in[1];
    const float* wk  = (const float*)d_in[2];
    const float* wv  = (const float*)d_in[3];
    const float* wo  = (const float*)d_in[4];
    const int*   pos = (const int*)d_in[5];
    float* out = (float*)d_out;

    float *q, *k, *v;
    cudaGetSymbolAddress((void**)&q, g_q);
    cudaGetSymbolAddress((void**)&k, g_k);
    cudaGetSymbolAddress((void**)&v, g_v);

    __nv_bfloat16 *xh, *xl, *wqh, *wql, *wkh, *wkl, *wvh, *wvl, *woh, *wol;
    __nv_bfloat16 *vhh, *vll, *ah, *al;
    cudaGetSymbolAddress((void**)&xh,  g_xh);  cudaGetSymbolAddress((void**)&xl,  g_xl);
    cudaGetSymbolAddress((void**)&wqh, g_wqh); cudaGetSymbolAddress((void**)&wql, g_wql);
    cudaGetSymbolAddress((void**)&wkh, g_wkh); cudaGetSymbolAddress((void**)&wkl, g_wkl);
    cudaGetSymbolAddress((void**)&wvh, g_wvh); cudaGetSymbolAddress((void**)&wvl, g_wvl);
    cudaGetSymbolAddress((void**)&woh, g_woh); cudaGetSymbolAddress((void**)&wol, g_wol);
    cudaGetSymbolAddress((void**)&vhh, g_vhh); cudaGetSymbolAddress((void**)&vll, g_vll);
    cudaGetSymbolAddress((void**)&ah,  g_ah);  cudaGetSymbolAddress((void**)&al,  g_al);

    cudaFuncSetAttribute((const void*)gemm_bf16x3_kernel,
                         cudaFuncAttributeMaxDynamicSharedMemorySize,
                         GEMM_SMEM_BYTES);
    cudaFuncSetAttribute((const void*)attn_kernel,
                         cudaFuncAttributeMaxDynamicSharedMemorySize,
                         ATT_SMEM_BYTES);

    // Split inputs to bf16 hi/lo
    {
        int n4;
        n4 = MROWS * Dn / 4;  split_kernel<<<(n4 + 255) / 256, 256>>>(x,  xh,  xl,  n4);
        n4 = Dn * Dn / 4;     split_kernel<<<(n4 + 255) / 256, 256>>>(wq, wqh, wql, n4);
        n4 = Dn * NKV / 4;    split_kernel<<<(n4 + 255) / 256, 256>>>(wk, wkh, wkl, n4);
        n4 = Dn * NKV / 4;    split_kernel<<<(n4 + 255) / 256, 256>>>(wv, wvh, wvl, n4);
        n4 = Dn * Dn / 4;     split_kernel<<<(n4 + 255) / 256, 256>>>(wo, woh, wol, n4);
    }

    dim3 gq(Dn / 128, MROWS / 128);
    dim3 gkv(NKV / 128, MROWS / 128);

    gemm_bf16x3_kernel<<<gq, 256, GEMM_SMEM_BYTES>>>(xh, xl, wqh, wql, q, Dn, Dn);
    gemm_bf16x3_kernel<<<gkv, 256, GEMM_SMEM_BYTES>>>(xh, xl, wkh, wkl, k, NKV, Dn);
    gemm_bf16x3_kernel<<<gkv, 256, GEMM_SMEM_BYTES>>>(xh, xl, wvh, wvl, v, NKV, Dn);

    {
        int tq = MROWS * HQn * 32;
        rope_split_q<<<(tq + 255) / 256, 256>>>(pos);
        dim3 gk2(Ln / 128, HKVn * 32, Bn);
        rope_split_kT<<<gk2, 128>>>(pos);
        int n4 = MROWS * NKV / 4;
        split_kernel<<<(n4 + 255) / 256, 256>>>(v, vhh, vll, n4);
    }

    dim3 ga(Ln / 64, HQn, Bn);
    attn_kernel<<<ga, 128, ATT_SMEM_BYTES>>>();

    gemm_bf16x3_kernel<<<gq, 256, GEMM_SMEM_BYTES>>>(ah, al, woh, wol, out, Dn, Dn);
}